// round 9
// baseline (speedup 1.0000x reference)
#include <cuda_runtime.h>

#define BB 8
#define CI 128
#define MC 64
#define HH 64
#define WW 64
#define NH 128
#define NW 128
#define OP 112   // encoder outputs padded 100 -> 112 (14 o-tiles of 8)
#define XST 18   // carafe x_s channel-minor row stride (even -> aligned ld2)

// Scratch (allocation-free per harness rules)
__device__ float g_m[BB * MC * HH * WW];                 // compressed features
__device__ float g_ker[BB * 25 * NH * NW];               // softmax kernels
__device__ __align__(16) float g_ew2t[MC * 9 * OP];      // weights [c][tap][o]
__device__ __align__(16) float g_cw2[CI * MC];           // compress weights [c][m]

typedef unsigned long long u64;

__device__ __forceinline__ u64 pk2(float lo, float hi) {
    u64 r; asm("mov.b64 %0, {%1,%2};" : "=l"(r) : "f"(lo), "f"(hi)); return r;
}
__device__ __forceinline__ float2 upk2(u64 v) {
    float2 f; asm("mov.b64 {%0,%1}, %2;" : "=f"(f.x), "=f"(f.y) : "l"(v)); return f;
}
__device__ __forceinline__ void fma2(u64 &acc, u64 a, u64 b) {
    asm("fma.rn.f32x2 %0, %1, %2, %0;" : "+l"(acc) : "l"(a), "l"(b));
}
__device__ __forceinline__ u64 ld2(const float* p) {
    return *reinterpret_cast<const u64*>(p);
}

// ---------------------------------------------------------------------------
// Prep: weight transposes. g_ew2t[c][tap][o] (o zero-padded to 112), g_cw2[c][m].
// ---------------------------------------------------------------------------
__global__ __launch_bounds__(256)
void k_prep(const float* __restrict__ ew, const float* __restrict__ cw) {
    int idx = blockIdx.x * 256 + threadIdx.x;
    const int n1 = MC * 9 * OP;
    if (idx < n1) {
        int c = idx / (9 * OP);
        int rem = idx - c * 9 * OP;
        int tap = rem / OP, o = rem - tap * OP;
        g_ew2t[idx] = (o < 100) ? ew[o * 576 + c * 9 + tap] : 0.f;
    } else if (idx < n1 + CI * MC) {
        int j = idx - n1;
        int c = j >> 6, m = j & 63;
        g_cw2[j] = cw[m * CI + c];
    }
}

// ---------------------------------------------------------------------------
// Kernel 1: 1x1 compress conv. block=(h,b) single row, 128 thr, grid 512,
// smem 67.6 KB -> 3 blocks/SM (12 warps). Thread = (mt 0..15 -> 4 m,
// wt 0..7 -> 8 w). Per c: 4 X ld2 (8-addr dedup) + 4 W scalar broadcast +
// 16 fma2  (~17 B/fma2, fma-bound).
// ---------------------------------------------------------------------------
extern __shared__ float sm1[];
__global__ __launch_bounds__(128)
void k_compress(const float* __restrict__ x, const float* __restrict__ cb) {
    float* xs = sm1;                 // CI*68
    float* ws = sm1 + CI * 68;       // CI*64
    const int h = blockIdx.x, b = blockIdx.y, tid = threadIdx.x;

    const float4* x4 = reinterpret_cast<const float4*>(x) + (size_t)b * (CI * HH * WW / 4);
    for (int idx = tid; idx < CI * 16; idx += 128) {
        int q = idx & 15, c = idx >> 4;
        float4 v = x4[(c * HH + h) * 16 + q];
        *reinterpret_cast<float4*>(xs + c * 68 + q * 4) = v;
    }
    for (int idx = tid; idx < CI * MC / 4; idx += 128)
        reinterpret_cast<float4*>(ws)[idx] = reinterpret_cast<const float4*>(g_cw2)[idx];
    __syncthreads();

    const int mt = tid >> 3, wt = tid & 7;
    const int m0 = mt * 4, w0 = wt * 8;

    u64 acc[4][4];   // [wp][m]
    #pragma unroll
    for (int wp = 0; wp < 4; wp++)
        #pragma unroll
        for (int m = 0; m < 4; m++) acc[wp][m] = 0;

    #pragma unroll 2
    for (int c = 0; c < CI; c++) {
        const float* xr = xs + c * 68 + w0;
        u64 X0 = ld2(xr), X1 = ld2(xr + 2), X2 = ld2(xr + 4), X3 = ld2(xr + 6);
        const float* wr = ws + c * 64 + m0;
        #pragma unroll
        for (int m = 0; m < 4; m++) {
            float wv = wr[m];
            u64 W = pk2(wv, wv);
            fma2(acc[0][m], X0, W); fma2(acc[1][m], X1, W);
            fma2(acc[2][m], X2, W); fma2(acc[3][m], X3, W);
        }
    }
    #pragma unroll
    for (int m = 0; m < 4; m++) {
        float bv = cb[m0 + m];
        #pragma unroll
        for (int wp = 0; wp < 4; wp++) {
            float2 v = upk2(acc[wp][m]);
            *reinterpret_cast<float2*>(
                g_m + (((size_t)b * MC + m0 + m) * HH + h) * WW + w0 + 2 * wp)
                = make_float2(v.x + bv, v.y + bv);
        }
    }
}

// ---------------------------------------------------------------------------
// Kernel 2: 3x3 encoder conv + bias + pixel-shuffle + softmax. (R4/R8 best
// measured version, frozen.) block=(h,b), 224 thr = 14 o-tiles(8) x 16 w-tiles(4).
// ---------------------------------------------------------------------------
extern __shared__ float sm2[];
__global__ __launch_bounds__(224)
void k_encoder(const float* __restrict__ eb) {
    float* m_s = sm2;                 // 8*3*72 = 1728
    float* w_s = sm2 + 1728;          // 8*9*112 = 8064
    float* kt  = sm2;                 // alias, 112*64 = 7168
    const int h = blockIdx.x, b = blockIdx.y, tid = threadIdx.x;
    const int ot = tid >> 4, wt = tid & 15;
    const int o0 = ot * 8, w0 = wt * 4;

    u64 acc[4][4];   // [o-pair][w]
    #pragma unroll
    for (int j = 0; j < 4; j++) {
        int o = o0 + 2 * j;
        float b0 = (o < 100) ? __ldg(eb + o) : 0.f;
        float b1 = (o + 1 < 100) ? __ldg(eb + o + 1) : 0.f;
        u64 bb = pk2(b0, b1);
        #pragma unroll
        for (int k = 0; k < 4; k++) acc[j][k] = bb;
    }

    for (int cc0 = 0; cc0 < MC; cc0 += 8) {
        __syncthreads();
        for (int idx = tid; idx < 24 * 16; idx += 224) {
            int q = idx & 15, row = idx >> 4;       // row = c*3 + r
            int c = row / 3, r = row - c * 3;
            int hh = h + r - 1;
            float4 v = make_float4(0.f, 0.f, 0.f, 0.f);
            if ((unsigned)hh < HH)
                v = *reinterpret_cast<const float4*>(
                    g_m + (((size_t)b * MC + cc0 + c) * HH + hh) * WW + q * 4);
            *reinterpret_cast<float4*>(m_s + row * 72 + 4 + q * 4) = v;
        }
        for (int idx = tid; idx < 48; idx += 224) {
            int row = idx >> 1, e = idx & 1;
            *reinterpret_cast<float4*>(m_s + row * 72 + (e ? 68 : 0)) =
                make_float4(0.f, 0.f, 0.f, 0.f);
        }
        {
            const float4* wsrc = reinterpret_cast<const float4*>(g_ew2t + cc0 * 9 * OP);
            for (int idx = tid; idx < 8 * 9 * OP / 4; idx += 224)
                reinterpret_cast<float4*>(w_s)[idx] = wsrc[idx];
        }
        __syncthreads();

        #pragma unroll 1
        for (int c = 0; c < 8; c++) {
            #pragma unroll
            for (int r = 0; r < 3; r++) {
                const float* mr = m_s + (c * 3 + r) * 72 + w0;
                float4 A = *reinterpret_cast<const float4*>(mr);
                float4 Bv = *reinterpret_cast<const float4*>(mr + 4);
                float4 Cv = *reinterpret_cast<const float4*>(mr + 8);
                float xv[7];
                xv[0] = A.w;
                xv[1] = Bv.x; xv[2] = Bv.y; xv[3] = Bv.z; xv[4] = Bv.w;
                xv[5] = Cv.x; xv[6] = Cv.y;
                #pragma unroll
                for (int s = 0; s < 3; s++) {
                    const float* wr = w_s + (c * 9 + r * 3 + s) * OP + o0;
                    u64 W0 = ld2(wr), W1 = ld2(wr + 2), W2 = ld2(wr + 4), W3 = ld2(wr + 6);
                    #pragma unroll
                    for (int k = 0; k < 4; k++) {
                        u64 X = pk2(xv[k + s], xv[k + s]);
                        fma2(acc[0][k], X, W0);
                        fma2(acc[1][k], X, W1);
                        fma2(acc[2][k], X, W2);
                        fma2(acc[3][k], X, W3);
                    }
                }
            }
        }
    }
    __syncthreads();
    #pragma unroll
    for (int j = 0; j < 4; j++)
        #pragma unroll
        for (int k = 0; k < 4; k++) {
            float2 v = upk2(acc[j][k]);
            kt[(o0 + 2 * j) * 64 + w0 + k] = v.x;
            kt[(o0 + 2 * j + 1) * 64 + w0 + k] = v.y;
        }
    __syncthreads();

    for (int task = tid; task < 256; task += 224) {
        int sub = task >> 6, w2 = task & 63;
        int sh = sub >> 1, sw = sub & 1;
        float v[25]; float mx = -1e30f;
        #pragma unroll
        for (int t = 0; t < 25; t++) { v[t] = kt[(t * 4 + sub) * 64 + w2]; mx = fmaxf(mx, v[t]); }
        float ssum = 0.f;
        #pragma unroll
        for (int t = 0; t < 25; t++) { v[t] = __expf(v[t] - mx); ssum += v[t]; }
        float inv = 1.f / ssum;
        int oh = 2 * h + sh, ow = 2 * w2 + sw;
        #pragma unroll
        for (int t = 0; t < 25; t++)
            g_ker[(((size_t)b * 25 + t) * NH + oh) * NW + ow] = v[t] * inv;
    }
}

// ---------------------------------------------------------------------------
// Kernel 3: content-aware reassembly, ow-major / channel-minor.
// block=(h, cg, b): 16 channels, 256 thr = 128 ow x 2 cog(8 ch as 4 pairs).
// x_s[i][iw][c] stride-18 c-minor: lane pairs share w -> x ld2 dedups to
// 128 B; K scalar conflict-free. 96 B/warp-fma2, ~50 KB smem -> 4 blocks/SM.
// ---------------------------------------------------------------------------
extern __shared__ float sm3[];
__global__ __launch_bounds__(256, 4)
void k_carafe(const float* __restrict__ x, float* __restrict__ out) {
    float* ker_s = sm3;             // 50*128 = 6400
    float* x_s   = sm3 + 6400;      // 5*68*XST = 6120
    const int h = blockIdx.x, cg = blockIdx.y, b = blockIdx.z, tid = threadIdx.x;
    const int cbase = cg * 16;

    // stage ker rows (both oh of the pair) as float4
    for (int idx = tid; idx < 50 * 32; idx += 256) {
        int q = idx & 31, tp = idx >> 5;
        *reinterpret_cast<float4*>(ker_s + tp * 128 + q * 4) =
            *reinterpret_cast<const float4*>(
                g_ker + (((size_t)b * 25 + (tp >> 1)) * NH + 2 * h + (tp & 1)) * NW + q * 4);
    }
    // stage x channel-minor: [i][iw][c], iw = col + 2
    for (int idx = tid; idx < 16 * 5 * 16; idx += 256) {
        int q = idx & 15, i = (idx >> 4) % 5, c = idx / 80;
        int hh = h + i - 2;
        float4 v = make_float4(0.f, 0.f, 0.f, 0.f);
        if ((unsigned)hh < HH)
            v = *reinterpret_cast<const float4*>(
                x + (((size_t)b * CI + cbase + c) * HH + hh) * WW + q * 4);
        float* dst = x_s + (i * 68 + q * 4 + 2) * XST + c;
        dst[0] = v.x; dst[XST] = v.y; dst[2 * XST] = v.z; dst[3 * XST] = v.w;
    }
    // zero halo iw in {0,1,66,67}
    for (int idx = tid; idx < 5 * 4 * 16; idx += 256) {
        int c = idx & 15, e = (idx >> 4) & 3, i = idx >> 6;
        int iw = (e < 2) ? e : 64 + e;
        x_s[(i * 68 + iw) * XST + c] = 0.f;
    }
    __syncthreads();

    const int ow = tid & 127, cog = tid >> 7;
    const int w = ow >> 1;
    const float* kb = ker_s + ow;
    const float* xb = x_s + w * XST + cog * 8;

    u64 acc[2][4];   // [p][c-pair]
    #pragma unroll
    for (int p = 0; p < 2; p++)
        #pragma unroll
        for (int cp = 0; cp < 4; cp++) acc[p][cp] = 0;

    #pragma unroll
    for (int i = 0; i < 5; i++) {
        #pragma unroll
        for (int j = 0; j < 5; j++) {
            const int t = i * 5 + j;
            float k0 = kb[(2 * t) * 128];
            float k1 = kb[(2 * t + 1) * 128];
            u64 K0 = pk2(k0, k0), K1 = pk2(k1, k1);
            const float* xp = xb + (i * 68 + j) * XST;
            #pragma unroll
            for (int cp = 0; cp < 4; cp++) {
                u64 X = ld2(xp + 2 * cp);
                fma2(acc[0][cp], X, K0);
                fma2(acc[1][cp], X, K1);
            }
        }
    }
    #pragma unroll
    for (int p = 0; p < 2; p++)
        #pragma unroll
        for (int cp = 0; cp < 4; cp++) {
            float2 v = upk2(acc[p][cp]);
            int ch = cbase + cog * 8 + 2 * cp;
            size_t base = (((size_t)b * CI + ch) * NH + 2 * h + p) * NW + ow;
            out[base] = v.x;
            out[base + (size_t)NH * NW] = v.y;
        }
}

// ---------------------------------------------------------------------------
extern "C" void kernel_launch(void* const* d_in, const int* in_sizes, int n_in,
                              void* d_out, int out_size) {
    const float* x  = (const float*)d_in[0];
    const float* cw = (const float*)d_in[1];
    const float* cb = (const float*)d_in[2];
    const float* ew = (const float*)d_in[3];
    const float* eb = (const float*)d_in[4];
    float* out = (float*)d_out;

    const int smem1 = (CI * 68 + CI * MC) * 4;         // 67584
    const int smem2 = (1728 + 8064) * 4;               // 39168
    const int smem3 = (6400 + 5 * 68 * XST) * 4;       // 50080
    cudaFuncSetAttribute(k_compress, cudaFuncAttributeMaxDynamicSharedMemorySize, smem1);
    cudaFuncSetAttribute(k_encoder,  cudaFuncAttributeMaxDynamicSharedMemorySize, smem2);
    cudaFuncSetAttribute(k_carafe,   cudaFuncAttributeMaxDynamicSharedMemorySize, smem3);

    k_prep<<<(MC * 9 * OP + CI * MC + 255) / 256, 256>>>(ew, cw);
    k_compress<<<dim3(HH, BB), 128, smem1>>>(x, cb);
    k_encoder<<<dim3(HH, BB), 224, smem2>>>(eb);
    k_carafe<<<dim3(HH, 8, BB), 256, smem3>>>(x, out);
}

// round 11
// speedup vs baseline: 1.0241x; 1.0241x over previous
#include <cuda_runtime.h>
#include <cstdint>

#define BB 8
#define CI 128
#define MC 64
#define HH 64
#define WW 64
#define NH 128
#define NW 128
#define KTOT 576       // encoder GEMM K = 64c * 9taps
#define KC 48          // k per chunk (6 ksteps of 8)
#define NCH 12
#define A_CH 12288     // u32 per A chunk: 2 parts * 8 mt * 6 ks * 32 t * 4
#define B_CH 12288     // u32 per B chunk: 2 parts * 6 ks * 16 nt * 32 t * 2
#define SMEM_ENC ((A_CH + B_CH) * 4)   // 98304 B

// Scratch (allocation-free per harness rules)
__device__ float g_m[BB * MC * HH * WW];                   // compressed features
__device__ float g_ker[BB * 25 * NH * NW];                 // softmax kernels
__device__ __align__(16) float g_cw2[CI * MC];             // compress weights [c][m]
__device__ __align__(16) uint32_t g_afrag[NCH * A_CH];     // A fragment images (hi/lo tf32)

typedef unsigned long long u64;

__device__ __forceinline__ u64 pk2(float lo, float hi) {
    u64 r; asm("mov.b64 %0, {%1,%2};" : "=l"(r) : "f"(lo), "f"(hi)); return r;
}
__device__ __forceinline__ float2 upk2(u64 v) {
    float2 f; asm("mov.b64 {%0,%1}, %2;" : "=f"(f.x), "=f"(f.y) : "l"(v)); return f;
}
__device__ __forceinline__ void fma2(u64 &acc, u64 a, u64 b) {
    asm("fma.rn.f32x2 %0, %1, %2, %0;" : "+l"(acc) : "l"(a), "l"(b));
}
__device__ __forceinline__ u64 ld2(const float* p) {
    return *reinterpret_cast<const u64*>(p);
}
__device__ __forceinline__ uint32_t tf32r(float v) {
    uint32_t r; asm("cvt.rna.tf32.f32 %0, %1;" : "=r"(r) : "f"(v)); return r;
}
__device__ __forceinline__ void mma8(float* d, const uint4 a, const uint2 b) {
    asm("mma.sync.aligned.m16n8k8.row.col.f32.tf32.tf32.f32 "
        "{%0,%1,%2,%3}, {%4,%5,%6,%7}, {%8,%9}, {%0,%1,%2,%3};"
        : "+f"(d[0]), "+f"(d[1]), "+f"(d[2]), "+f"(d[3])
        : "r"(a.x), "r"(a.y), "r"(a.z), "r"(a.w), "r"(b.x), "r"(b.y));
}

// ---------------------------------------------------------------------------
// Prep: encoder weights -> per-chunk fragment images (tf32 hi/lo, o padded
// to 128); compress weights -> [c][m].
// A frag mapping (m16n8k8 row-major A): thread t=g*4+tig holds
//   a0=(g,tig) a1=(g+8,tig) a2=(g,tig+4) a3=(g+8,tig+4)  [row=o%16, col=k%8]
// ---------------------------------------------------------------------------
__global__ __launch_bounds__(256)
void k_prep(const float* __restrict__ ew, const float* __restrict__ cw) {
    int idx = blockIdx.x * 256 + threadIdx.x;
    if (idx < 128 * KTOT) {
        int o = idx / KTOT, k = idx - o * KTOT;
        float v = (o < 100) ? ew[o * KTOT + k] : 0.f;
        int ch = k / KC, kl = k - ch * KC;
        int ks = kl >> 3, kk = kl & 7;
        int mt = o >> 4, mr = o & 15;
        int t = (mr & 7) * 4 + (kk & 3);
        int reg = (kk >> 2) * 2 + (mr >> 3);
        int off = ((mt * 6 + ks) * 32 + t) * 4 + reg;
        uint32_t vh = tf32r(v);
        float vl = v - __uint_as_float(vh);
        g_afrag[ch * A_CH + off] = vh;
        g_afrag[ch * A_CH + 6144 + off] = tf32r(vl);
    } else if (idx < 128 * KTOT + CI * MC) {
        int j = idx - 128 * KTOT;
        g_cw2[j] = cw[(j & 63) * CI + (j >> 6)];
    }
}

// ---------------------------------------------------------------------------
// Kernel 1: 1x1 compress conv. block=(h-pair, b), 128 thr (R8 frozen).
// ---------------------------------------------------------------------------
extern __shared__ float sm1[];
__global__ __launch_bounds__(128)
void k_compress(const float* __restrict__ x, const float* __restrict__ cb) {
    float* xs = sm1;
    float* ws = sm1 + CI * 2 * 68;
    const int hb = blockIdx.x, b = blockIdx.y, tid = threadIdx.x;

    const float4* x4 = reinterpret_cast<const float4*>(x) + (size_t)b * (CI * HH * WW / 4);
    for (int idx = tid; idx < CI * 2 * 16; idx += 128) {
        int q = idx & 15, r = (idx >> 4) & 1, c = idx >> 5;
        float4 v = x4[(c * HH + 2 * hb + r) * 16 + q];
        *reinterpret_cast<float4*>(xs + (c * 2 + r) * 68 + q * 4) = v;
    }
    for (int idx = tid; idx < CI * MC / 4; idx += 128)
        reinterpret_cast<float4*>(ws)[idx] = reinterpret_cast<const float4*>(g_cw2)[idx];
    __syncthreads();

    const int mt = tid >> 4, wt = tid & 15;
    const int r = wt >> 3, w0 = (wt & 7) * 8, m0 = mt * 8;

    u64 acc[4][8];
    #pragma unroll
    for (int m = 0; m < 8; m++)
        #pragma unroll
        for (int wp = 0; wp < 4; wp++) acc[wp][m] = 0;

    #pragma unroll 2
    for (int c = 0; c < CI; c++) {
        const float* xr = xs + (c * 2 + r) * 68 + w0;
        u64 X0 = ld2(xr), X1 = ld2(xr + 2), X2 = ld2(xr + 4), X3 = ld2(xr + 6);
        const float* wr = ws + c * 64 + m0;
        #pragma unroll
        for (int m = 0; m < 8; m++) {
            float wv = wr[m];
            u64 W = pk2(wv, wv);
            fma2(acc[0][m], X0, W); fma2(acc[1][m], X1, W);
            fma2(acc[2][m], X2, W); fma2(acc[3][m], X3, W);
        }
    }
    #pragma unroll
    for (int m = 0; m < 8; m++) {
        float bv = cb[m0 + m];
        #pragma unroll
        for (int wp = 0; wp < 4; wp++) {
            float2 v = upk2(acc[wp][m]);
            *reinterpret_cast<float2*>(
                g_m + (((size_t)b * MC + m0 + m) * HH + 2 * hb + r) * WW + w0 + 2 * wp)
                = make_float2(v.x + bv, v.y + bv);
        }
    }
}

// ---------------------------------------------------------------------------
// Kernel 2: encoder conv as tf32x3 mma.sync GEMM + bias + softmax.
// block=(h2,b) covers an h-pair. D[128o, 128n] (n = p*64 + w), K=576 in 12
// chunks of 48. Warps = 4 m-groups(32 rows) x 2 n-groups(64 cols).
// B frag mapping (col-major B, k x n): t=g*4+tig holds b0=(tig,g) b1=(tig+4,g).
// ---------------------------------------------------------------------------
__global__ __launch_bounds__(256, 2)
void k_encoder(const float* __restrict__ eb) {
    extern __shared__ __align__(16) uint32_t smE[];
    uint32_t* a_s = smE;             // A_CH u32
    uint32_t* b_s = smE + A_CH;      // B_CH u32
    float* kt = reinterpret_cast<float*>(smE);   // alias post-compute: [o][128]
    const int h2 = blockIdx.x, b = blockIdx.y, tid = threadIdx.x;
    const int wid = tid >> 5, lane = tid & 31;
    const int mg = wid >> 1, ngrp = wid & 1;
    const int gg = lane >> 2, tig = lane & 3;

    float acc[2][8][4];
    #pragma unroll
    for (int mt = 0; mt < 2; mt++)
        #pragma unroll
        for (int nt = 0; nt < 8; nt++)
            #pragma unroll
            for (int q = 0; q < 4; q++) acc[mt][nt][q] = 0.f;

    for (int ch = 0; ch < NCH; ch++) {
        __syncthreads();
        // stage A fragment image
        {
            const uint4* asrc = reinterpret_cast<const uint4*>(g_afrag + (size_t)ch * A_CH);
            uint4* adst = reinterpret_cast<uint4*>(a_s);
            for (int idx = tid; idx < A_CH / 4; idx += 256) adst[idx] = asrc[idx];
        }
        // build B fragment slots from g_m (hi & lo)
        for (int idx = tid; idx < KC * 128; idx += 256) {
            int n = idx & 127, kl = idx >> 7;
            int k = ch * KC + kl;
            int c = k / 9, rem = k - c * 9;
            int r = rem / 3, s = rem - r * 3;
            int p = n >> 6, w = n & 63;
            int hh = 2 * h2 + p + r - 1, col = w + s - 1;
            float v = 0.f;
            if ((unsigned)hh < HH && (unsigned)col < WW)
                v = g_m[(((size_t)b * MC + c) * HH + hh) * WW + col];
            uint32_t vh = tf32r(v);
            float vl = v - __uint_as_float(vh);
            int ks = kl >> 3, kk = kl & 7, nt = n >> 3, g = n & 7;
            int base = ((ks * 16 + nt) * 32 + g * 4 + (kk & 3)) * 2 + (kk >> 2);
            b_s[base] = vh;
            b_s[6144 + base] = tf32r(vl);
        }
        __syncthreads();

        #pragma unroll 1
        for (int ks = 0; ks < 6; ks++) {
            uint4 Ah[2], Al[2];
            #pragma unroll
            for (int mt = 0; mt < 2; mt++) {
                int mtg = mg * 2 + mt;
                Ah[mt] = *reinterpret_cast<const uint4*>(a_s + ((mtg * 6 + ks) * 32 + lane) * 4);
                Al[mt] = *reinterpret_cast<const uint4*>(a_s + (((8 + mtg) * 6 + ks) * 32 + lane) * 4);
            }
            #pragma unroll
            for (int nt = 0; nt < 8; nt++) {
                int ntg = ngrp * 8 + nt;
                uint2 Bh = *reinterpret_cast<const uint2*>(b_s + ((ks * 16 + ntg) * 32 + lane) * 2);
                uint2 Bl = *reinterpret_cast<const uint2*>(b_s + 6144 + ((ks * 16 + ntg) * 32 + lane) * 2);
                #pragma unroll
                for (int mt = 0; mt < 2; mt++) {
                    mma8(acc[mt][nt], Ah[mt], Bh);
                    mma8(acc[mt][nt], Ah[mt], Bl);
                    mma8(acc[mt][nt], Al[mt], Bh);
                }
            }
        }
    }
    __syncthreads();

    // writeout D -> kt[o][n] (+bias), per fragment mapping
    #pragma unroll
    for (int mt = 0; mt < 2; mt++) {
        #pragma unroll
        for (int nt = 0; nt < 8; nt++) {
            int o0 = (mg * 2 + mt) * 16 + gg;
            int n0 = (ngrp * 8 + nt) * 8 + 2 * tig;
            const float* c = acc[mt][nt];
            if (o0 < 100) {
                float bv = __ldg(eb + o0);
                kt[o0 * 128 + n0] = c[0] + bv;
                kt[o0 * 128 + n0 + 1] = c[1] + bv;
            }
            int o1 = o0 + 8;
            if (o1 < 100) {
                float bv = __ldg(eb + o1);
                kt[o1 * 128 + n0] = c[2] + bv;
                kt[o1 * 128 + n0 + 1] = c[3] + bv;
            }
        }
    }
    __syncthreads();

    // softmax over 25 taps: 512 tasks = p(2) x sub(4) x w(64)
    for (int task = tid; task < 512; task += 256) {
        int w2 = task & 63, sub = (task >> 6) & 3, p = task >> 8;
        int colk = p * 64 + w2;
        int sh = sub >> 1, sw = sub & 1;
        float v[25]; float mx = -1e30f;
        #pragma unroll
        for (int t = 0; t < 25; t++) {
            v[t] = kt[(t * 4 + sub) * 128 + colk];
            mx = fmaxf(mx, v[t]);
        }
        float ssum = 0.f;
        #pragma unroll
        for (int t = 0; t < 25; t++) { v[t] = __expf(v[t] - mx); ssum += v[t]; }
        float inv = 1.f / ssum;
        int oh = 4 * h2 + 2 * p + sh, ow = 2 * w2 + sw;
        #pragma unroll
        for (int t = 0; t < 25; t++)
            g_ker[(((size_t)b * 25 + t) * NH + oh) * NW + ow] = v[t] * inv;
    }
}

// ---------------------------------------------------------------------------
// Kernel 3: content-aware reassembly (R8 frozen). block=(h, cg, b): 16 ch,
// 256 thr, ~48 KB smem -> 4 blocks/SM.
// ---------------------------------------------------------------------------
extern __shared__ float sm3[];
__global__ __launch_bounds__(256, 4)
void k_carafe(const float* __restrict__ x, float* __restrict__ out) {
    float* ker_s = sm3;           // 50*128
    float* x_s   = sm3 + 6400;    // 80*72
    const int h = blockIdx.x, cg = blockIdx.y, b = blockIdx.z, tid = threadIdx.x;
    const int cbase = cg * 16;

    for (int idx = tid; idx < 50 * 32; idx += 256) {
        int q = idx & 31, tp = idx >> 5;
        *reinterpret_cast<float4*>(ker_s + tp * 128 + q * 4) =
            *reinterpret_cast<const float4*>(
                g_ker + (((size_t)b * 25 + (tp >> 1)) * NH + 2 * h + (tp & 1)) * NW + q * 4);
    }
    for (int idx = tid; idx < 16 * 5 * 16; idx += 256) {
        int q = idx & 15, row = idx >> 4;
        int c = row / 5, i = row - c * 5;
        int hh = h + i - 2;
        float4 v = make_float4(0.f, 0.f, 0.f, 0.f);
        if ((unsigned)hh < HH)
            v = *reinterpret_cast<const float4*>(
                x + (((size_t)b * CI + cbase + c) * HH + hh) * WW + q * 4);
        *reinterpret_cast<float4*>(x_s + row * 72 + 4 + q * 4) = v;
    }
    for (int idx = tid; idx < 160; idx += 256) {
        int row = idx >> 1, e = idx & 1;
        *reinterpret_cast<float4*>(x_s + row * 72 + (e ? 68 : 0)) =
            make_float4(0.f, 0.f, 0.f, 0.f);
    }
    __syncthreads();

    const int w = tid & 63, co = tid >> 6;
    const float* kb = ker_s + 2 * w;
    const float* xb = x_s + (size_t)(co * 4) * 360 + w + 2;

    u64 acc[2][4];
    #pragma unroll
    for (int p = 0; p < 2; p++)
        #pragma unroll
        for (int cc = 0; cc < 4; cc++) acc[p][cc] = 0;

    #pragma unroll
    for (int i = 0; i < 5; i++) {
        #pragma unroll
        for (int j = 0; j < 5; j++) {
            const int t = i * 5 + j;
            u64 K0 = ld2(kb + (2 * t) * 128);
            u64 K1 = ld2(kb + (2 * t + 1) * 128);
            #pragma unroll
            for (int cc = 0; cc < 4; cc++) {
                float xv = xb[cc * 360 + i * 72 + j];
                u64 X = pk2(xv, xv);
                fma2(acc[0][cc], X, K0);
                fma2(acc[1][cc], X, K1);
            }
        }
    }
    #pragma unroll
    for (int p = 0; p < 2; p++)
        #pragma unroll
        for (int cc = 0; cc < 4; cc++) {
            float2 v = upk2(acc[p][cc]);
            int ch = cbase + co * 4 + cc;
            *reinterpret_cast<float2*>(
                out + (((size_t)b * CI + ch) * NH + 2 * h + p) * NW + 2 * w) = v;
        }
}

// ---------------------------------------------------------------------------
extern "C" void kernel_launch(void* const* d_in, const int* in_sizes, int n_in,
                              void* d_out, int out_size) {
    const float* x  = (const float*)d_in[0];
    const float* cw = (const float*)d_in[1];
    const float* cb = (const float*)d_in[2];
    const float* ew = (const float*)d_in[3];
    const float* eb = (const float*)d_in[4];
    float* out = (float*)d_out;

    const int smem1 = (CI * 2 * 68 + CI * MC) * 4;     // 102400
    const int smem3 = (6400 + 80 * 72) * 4;            // 48640
    cudaFuncSetAttribute(k_compress, cudaFuncAttributeMaxDynamicSharedMemorySize, smem1);
    cudaFuncSetAttribute(k_encoder,  cudaFuncAttributeMaxDynamicSharedMemorySize, SMEM_ENC);
    cudaFuncSetAttribute(k_carafe,   cudaFuncAttributeMaxDynamicSharedMemorySize, smem3);

    k_prep<<<(128 * KTOT + CI * MC + 255) / 256, 256>>>(ew, cw);
    k_compress<<<dim3(HH / 2, BB), 128, smem1>>>(x, cb);
    k_encoder<<<dim3(HH / 2, BB), 256, SMEM_ENC>>>(eb);
    k_carafe<<<dim3(HH, 8, BB), 256, smem3>>>(x, out);
}

// round 12
// speedup vs baseline: 1.3135x; 1.2826x over previous
#include <cuda_runtime.h>
#include <cuda_fp16.h>
#include <cstdint>

#define BB 8
#define CI 128
#define MC 64
#define HH 64
#define WW 64
#define NH 128
#define NW 128
#define KTOT 576       // encoder GEMM K = 64c * 9taps
#define KC 48          // k per chunk (3 ksteps of 16)
#define NCH 12
#define A_CH16 12288   // u16 per A chunk: 2 parts * 8 mt * 3 ks * 32 lanes * 4 regs * 2
#define B_CH16 6144    // u16 per B chunk: 3 ks * 16 ntg * 32 lanes * 2 regs * 2
#define SMEM_ENC 51456 // kt alias (100*128 f32) dominates A+B images (36864 B)

// Scratch (allocation-free per harness rules)
__device__ float g_m[BB * MC * HH * WW];                   // compressed features
__device__ float g_ker[BB * 25 * NH * NW];                 // softmax kernels
__device__ __align__(16) float g_cw2[CI * MC];             // compress weights [c][m]
__device__ __align__(16) uint16_t g_afrag[NCH * A_CH16];   // A fragment images (fp16 hi/lo)

typedef unsigned long long u64;

__device__ __forceinline__ u64 pk2(float lo, float hi) {
    u64 r; asm("mov.b64 %0, {%1,%2};" : "=l"(r) : "f"(lo), "f"(hi)); return r;
}
__device__ __forceinline__ float2 upk2(u64 v) {
    float2 f; asm("mov.b64 {%0,%1}, %2;" : "=f"(f.x), "=f"(f.y) : "l"(v)); return f;
}
__device__ __forceinline__ void fma2(u64 &acc, u64 a, u64 b) {
    asm("fma.rn.f32x2 %0, %1, %2, %0;" : "+l"(acc) : "l"(a), "l"(b));
}
__device__ __forceinline__ u64 ld2(const float* p) {
    return *reinterpret_cast<const u64*>(p);
}
__device__ __forceinline__ void mma16(float* d, const uint4 a, const uint2 b) {
    asm("mma.sync.aligned.m16n8k16.row.col.f32.f16.f16.f32 "
        "{%0,%1,%2,%3}, {%4,%5,%6,%7}, {%8,%9}, {%0,%1,%2,%3};"
        : "+f"(d[0]), "+f"(d[1]), "+f"(d[2]), "+f"(d[3])
        : "r"(a.x), "r"(a.y), "r"(a.z), "r"(a.w), "r"(b.x), "r"(b.y));
}

// ---------------------------------------------------------------------------
// Prep: encoder weights -> per-chunk fp16 fragment images (hi + residual lo,
// o padded to 128); compress weights -> [c][m].
// m16n8k16 A frag (row-major): lane = g*4+tig holds
//   reg = (kk>=8)*2 + (o16>=8), pair cols (2tig, 2tig+1) [+8 if kk>=8]
// ---------------------------------------------------------------------------
__global__ __launch_bounds__(256)
void k_prep(const float* __restrict__ ew, const float* __restrict__ cw) {
    int idx = blockIdx.x * 256 + threadIdx.x;
    if (idx < 128 * KTOT) {
        int o = idx / KTOT, k = idx - o * KTOT;
        float v = (o < 100) ? ew[o * KTOT + k] : 0.f;
        int ch = k / KC, kl = k - ch * KC;
        int ks = kl >> 4, kk = kl & 15;
        int mt = o >> 4, o16 = o & 15;
        int reg = ((kk >> 3) << 1) | (o16 >> 3);
        int lane = (o16 & 7) * 4 + ((kk >> 1) & 3);
        int half = kk & 1;
        __half h1 = __float2half_rn(v);
        __half h2 = __float2half_rn(v - __half2float(h1));
        int base0 = ((((0 * 8 + mt) * 3 + ks) * 32 + lane) * 4 + reg) * 2 + half;
        int base1 = ((((8 + mt) * 3 + ks) * 32 + lane) * 4 + reg) * 2 + half;
        g_afrag[ch * A_CH16 + base0] = __half_as_ushort(h1);
        g_afrag[ch * A_CH16 + base1] = __half_as_ushort(h2);
    } else if (idx < 128 * KTOT + CI * MC) {
        int j = idx - 128 * KTOT;
        g_cw2[j] = cw[(j & 63) * CI + (j >> 6)];
    }
}

// ---------------------------------------------------------------------------
// Kernel 1: 1x1 compress conv. block=(h-pair, b), 128 thr (R8 frozen).
// ---------------------------------------------------------------------------
extern __shared__ float sm1[];
__global__ __launch_bounds__(128)
void k_compress(const float* __restrict__ x, const float* __restrict__ cb) {
    float* xs = sm1;
    float* ws = sm1 + CI * 2 * 68;
    const int hb = blockIdx.x, b = blockIdx.y, tid = threadIdx.x;

    const float4* x4 = reinterpret_cast<const float4*>(x) + (size_t)b * (CI * HH * WW / 4);
    for (int idx = tid; idx < CI * 2 * 16; idx += 128) {
        int q = idx & 15, r = (idx >> 4) & 1, c = idx >> 5;
        float4 v = x4[(c * HH + 2 * hb + r) * 16 + q];
        *reinterpret_cast<float4*>(xs + (c * 2 + r) * 68 + q * 4) = v;
    }
    for (int idx = tid; idx < CI * MC / 4; idx += 128)
        reinterpret_cast<float4*>(ws)[idx] = reinterpret_cast<const float4*>(g_cw2)[idx];
    __syncthreads();

    const int mt = tid >> 4, wt = tid & 15;
    const int r = wt >> 3, w0 = (wt & 7) * 8, m0 = mt * 8;

    u64 acc[4][8];
    #pragma unroll
    for (int m = 0; m < 8; m++)
        #pragma unroll
        for (int wp = 0; wp < 4; wp++) acc[wp][m] = 0;

    #pragma unroll 2
    for (int c = 0; c < CI; c++) {
        const float* xr = xs + (c * 2 + r) * 68 + w0;
        u64 X0 = ld2(xr), X1 = ld2(xr + 2), X2 = ld2(xr + 4), X3 = ld2(xr + 6);
        const float* wr = ws + c * 64 + m0;
        #pragma unroll
        for (int m = 0; m < 8; m++) {
            float wv = wr[m];
            u64 W = pk2(wv, wv);
            fma2(acc[0][m], X0, W); fma2(acc[1][m], X1, W);
            fma2(acc[2][m], X2, W); fma2(acc[3][m], X3, W);
        }
    }
    #pragma unroll
    for (int m = 0; m < 8; m++) {
        float bv = cb[m0 + m];
        #pragma unroll
        for (int wp = 0; wp < 4; wp++) {
            float2 v = upk2(acc[wp][m]);
            *reinterpret_cast<float2*>(
                g_m + (((size_t)b * MC + m0 + m) * HH + 2 * hb + r) * WW + w0 + 2 * wp)
                = make_float2(v.x + bv, v.y + bv);
        }
    }
}

// ---------------------------------------------------------------------------
// Kernel 2: encoder conv as fp16x2 mma.sync GEMM + bias + softmax.
// block=(h2,b) covers an h-pair. D[128o,128n] (n = p*64 + w), K=576 in 12
// chunks of 48 (3 k16-steps). Warps = 4 m-groups x 2 n-groups.
// Products per step: A1*B + A2*B  (A = weight fp16 hi/lo split, B = fp16(m)).
// ---------------------------------------------------------------------------
__global__ __launch_bounds__(256, 2)
void k_encoder(const float* __restrict__ eb) {
    extern __shared__ __align__(16) uint32_t smE[];
    uint32_t* a_s = smE;             // 6144 u32 (A image: parts in mt dim 0-7 / 8-15)
    uint32_t* b_s = smE + 6144;      // 3072 u32
    uint16_t* b_s16 = reinterpret_cast<uint16_t*>(b_s);
    float* kt = reinterpret_cast<float*>(smE);   // alias post-compute: [o][128]
    const int h2 = blockIdx.x, b = blockIdx.y, tid = threadIdx.x;
    const int wid = tid >> 5, lane = tid & 31;
    const int mg = wid >> 1, ngrp = wid & 1;
    const int gg = lane >> 2, tig = lane & 3;

    float acc[2][8][4];
    #pragma unroll
    for (int mt = 0; mt < 2; mt++)
        #pragma unroll
        for (int nt = 0; nt < 8; nt++)
            #pragma unroll
            for (int q = 0; q < 4; q++) acc[mt][nt][q] = 0.f;

    for (int ch = 0; ch < NCH; ch++) {
        __syncthreads();
        // stage A fragment image (24.5 KB)
        {
            const uint4* asrc = reinterpret_cast<const uint4*>(g_afrag + (size_t)ch * A_CH16);
            uint4* adst = reinterpret_cast<uint4*>(a_s);
            for (int idx = tid; idx < A_CH16 / 8; idx += 256) adst[idx] = asrc[idx];
        }
        // build B fragment slots from g_m (single fp16 part)
        for (int idx = tid; idx < KC * 128; idx += 256) {
            int n = idx & 127, kl = idx >> 7;
            int k = ch * KC + kl;
            int c = k / 9, rem = k - c * 9;
            int r = rem / 3, s = rem - r * 3;
            int p = n >> 6, w = n & 63;
            int hh = 2 * h2 + p + r - 1, col = w + s - 1;
            float v = 0.f;
            if ((unsigned)hh < HH && (unsigned)col < WW)
                v = g_m[(((size_t)b * MC + c) * HH + hh) * WW + col];
            int ks = kl >> 4, kk = kl & 15;
            int ntg = n >> 3, n8 = n & 7;
            int reg = kk >> 3;
            int lne = n8 * 4 + ((kk >> 1) & 3);
            b_s16[(((ks * 16 + ntg) * 32 + lne) * 2 + reg) * 2 + (kk & 1)] =
                __half_as_ushort(__float2half_rn(v));
        }
        __syncthreads();

        #pragma unroll
        for (int ks = 0; ks < 3; ks++) {
            uint4 A1[2], A2[2];
            #pragma unroll
            for (int mt = 0; mt < 2; mt++) {
                int mtg = mg * 2 + mt;
                A1[mt] = *reinterpret_cast<const uint4*>(a_s + ((mtg * 3 + ks) * 32 + lane) * 4);
                A2[mt] = *reinterpret_cast<const uint4*>(a_s + (((8 + mtg) * 3 + ks) * 32 + lane) * 4);
            }
            #pragma unroll
            for (int nt = 0; nt < 8; nt++) {
                int ntg = ngrp * 8 + nt;
                uint2 Bv = *reinterpret_cast<const uint2*>(b_s + ((ks * 16 + ntg) * 32 + lane) * 2);
                #pragma unroll
                for (int mt = 0; mt < 2; mt++) {
                    mma16(acc[mt][nt], A1[mt], Bv);
                    mma16(acc[mt][nt], A2[mt], Bv);
                }
            }
        }
    }
    __syncthreads();

    // writeout D -> kt[o][n] (+bias), per fragment mapping
    #pragma unroll
    for (int mt = 0; mt < 2; mt++) {
        #pragma unroll
        for (int nt = 0; nt < 8; nt++) {
            int o0 = (mg * 2 + mt) * 16 + gg;
            int n0 = (ngrp * 8 + nt) * 8 + 2 * tig;
            const float* c = acc[mt][nt];
            if (o0 < 100) {
                float bv = __ldg(eb + o0);
                kt[o0 * 128 + n0] = c[0] + bv;
                kt[o0 * 128 + n0 + 1] = c[1] + bv;
            }
            int o1 = o0 + 8;
            if (o1 < 100) {
                float bv = __ldg(eb + o1);
                kt[o1 * 128 + n0] = c[2] + bv;
                kt[o1 * 128 + n0 + 1] = c[3] + bv;
            }
        }
    }
    __syncthreads();

    // softmax over 25 taps: 512 tasks = p(2) x sub(4) x w(64)
    for (int task = tid; task < 512; task += 256) {
        int w2 = task & 63, sub = (task >> 6) & 3, p = task >> 8;
        int colk = p * 64 + w2;
        int sh = sub >> 1, sw = sub & 1;
        float v[25]; float mx = -1e30f;
        #pragma unroll
        for (int t = 0; t < 25; t++) {
            v[t] = kt[(t * 4 + sub) * 128 + colk];
            mx = fmaxf(mx, v[t]);
        }
        float ssum = 0.f;
        #pragma unroll
        for (int t = 0; t < 25; t++) { v[t] = __expf(v[t] - mx); ssum += v[t]; }
        float inv = 1.f / ssum;
        int oh = 4 * h2 + 2 * p + sh, ow = 2 * w2 + sw;
        #pragma unroll
        for (int t = 0; t < 25; t++)
            g_ker[(((size_t)b * 25 + t) * NH + oh) * NW + ow] = v[t] * inv;
    }
}

// ---------------------------------------------------------------------------
// Kernel 3: content-aware reassembly (R8 frozen). block=(h, cg, b): 16 ch,
// 256 thr, ~48 KB smem -> 4 blocks/SM.
// ---------------------------------------------------------------------------
extern __shared__ float sm3[];
__global__ __launch_bounds__(256, 4)
void k_carafe(const float* __restrict__ x, float* __restrict__ out) {
    float* ker_s = sm3;           // 50*128
    float* x_s   = sm3 + 6400;    // 80*72
    const int h = blockIdx.x, cg = blockIdx.y, b = blockIdx.z, tid = threadIdx.x;
    const int cbase = cg * 16;

    for (int idx = tid; idx < 50 * 32; idx += 256) {
        int q = idx & 31, tp = idx >> 5;
        *reinterpret_cast<float4*>(ker_s + tp * 128 + q * 4) =
            *reinterpret_cast<const float4*>(
                g_ker + (((size_t)b * 25 + (tp >> 1)) * NH + 2 * h + (tp & 1)) * NW + q * 4);
    }
    for (int idx = tid; idx < 16 * 5 * 16; idx += 256) {
        int q = idx & 15, row = idx >> 4;
        int c = row / 5, i = row - c * 5;
        int hh = h + i - 2;
        float4 v = make_float4(0.f, 0.f, 0.f, 0.f);
        if ((unsigned)hh < HH)
            v = *reinterpret_cast<const float4*>(
                x + (((size_t)b * CI + cbase + c) * HH + hh) * WW + q * 4);
        *reinterpret_cast<float4*>(x_s + row * 72 + 4 + q * 4) = v;
    }
    for (int idx = tid; idx < 160; idx += 256) {
        int row = idx >> 1, e = idx & 1;
        *reinterpret_cast<float4*>(x_s + row * 72 + (e ? 68 : 0)) =
            make_float4(0.f, 0.f, 0.f, 0.f);
    }
    __syncthreads();

    const int w = tid & 63, co = tid >> 6;
    const float* kb = ker_s + 2 * w;
    const float* xb = x_s + (size_t)(co * 4) * 360 + w + 2;

    u64 acc[2][4];
    #pragma unroll
    for (int p = 0; p < 2; p++)
        #pragma unroll
        for (int cc = 0; cc < 4; cc++) acc[p][cc] = 0;

    #pragma unroll
    for (int i = 0; i < 5; i++) {
        #pragma unroll
        for (int j = 0; j < 5; j++) {
            const int t = i * 5 + j;
            u64 K0 = ld2(kb + (2 * t) * 128);
            u64 K1 = ld2(kb + (2 * t + 1) * 128);
            #pragma unroll
            for (int cc = 0; cc < 4; cc++) {
                float xv = xb[cc * 360 + i * 72 + j];
                u64 X = pk2(xv, xv);
                fma2(acc[0][cc], X, K0);
                fma2(acc[1][cc], X, K1);
            }
        }
    }
    #pragma unroll
    for (int p = 0; p < 2; p++)
        #pragma unroll
        for (int cc = 0; cc < 4; cc++) {
            float2 v = upk2(acc[p][cc]);
            int ch = cbase + co * 4 + cc;
            *reinterpret_cast<float2*>(
                out + (((size_t)b * CI + ch) * NH + 2 * h + p) * NW + 2 * w) = v;
        }
}

// ---------------------------------------------------------------------------
extern "C" void kernel_launch(void* const* d_in, const int* in_sizes, int n_in,
                              void* d_out, int out_size) {
    const float* x  = (const float*)d_in[0];
    const float* cw = (const float*)d_in[1];
    const float* cb = (const float*)d_in[2];
    const float* ew = (const float*)d_in[3];
    const float* eb = (const float*)d_in[4];
    float* out = (float*)d_out;

    const int smem1 = (CI * 2 * 68 + CI * MC) * 4;     // 102400
    const int smem3 = (6400 + 80 * 72) * 4;            // 48640
    cudaFuncSetAttribute(k_compress, cudaFuncAttributeMaxDynamicSharedMemorySize, smem1);
    cudaFuncSetAttribute(k_encoder,  cudaFuncAttributeMaxDynamicSharedMemorySize, SMEM_ENC);
    cudaFuncSetAttribute(k_carafe,   cudaFuncAttributeMaxDynamicSharedMemorySize, smem3);

    k_prep<<<(128 * KTOT + CI * MC + 255) / 256, 256>>>(ew, cw);
    k_compress<<<dim3(HH / 2, BB), 128, smem1>>>(x, cb);
    k_encoder<<<dim3(HH / 2, BB), 256, SMEM_ENC>>>(eb);
    k_carafe<<<dim3(HH, 8, BB), 256, smem3>>>(x, out);
}

// round 13
// speedup vs baseline: 1.4262x; 1.0858x over previous
#include <cuda_runtime.h>
#include <cuda_fp16.h>
#include <cstdint>

#define BB 8
#define CI 128
#define MC 64
#define HH 64
#define WW 64
#define NH 128
#define NW 128
#define KTOT 576       // encoder GEMM K = 64c * 9taps
#define KC 48          // k per chunk (3 ksteps of 16)
#define NCH 12
#define A_CH16 6144    // u16 per A chunk: 8 mt * 3 ks * 32 lanes * 4 regs * 2
#define SMEM_ENC 51456 // kt alias (100*128 f32) dominates A+B images (24576 B)

// Scratch (allocation-free per harness rules)
__device__ float g_m[BB * MC * HH * WW];                   // compressed features
__device__ float g_ker[BB * 25 * NH * NW];                 // softmax kernels
__device__ __align__(16) float g_cw2[CI * MC];             // compress weights [c][m]
__device__ __align__(16) uint16_t g_afrag[NCH * A_CH16];   // A fragment images (fp16)

typedef unsigned long long u64;

__device__ __forceinline__ u64 pk2(float lo, float hi) {
    u64 r; asm("mov.b64 %0, {%1,%2};" : "=l"(r) : "f"(lo), "f"(hi)); return r;
}
__device__ __forceinline__ float2 upk2(u64 v) {
    float2 f; asm("mov.b64 {%0,%1}, %2;" : "=f"(f.x), "=f"(f.y) : "l"(v)); return f;
}
__device__ __forceinline__ void fma2(u64 &acc, u64 a, u64 b) {
    asm("fma.rn.f32x2 %0, %1, %2, %0;" : "+l"(acc) : "l"(a), "l"(b));
}
__device__ __forceinline__ u64 ld2(const float* p) {
    return *reinterpret_cast<const u64*>(p);
}
__device__ __forceinline__ void mma16(float* d, const uint4 a, const uint2 b) {
    asm("mma.sync.aligned.m16n8k16.row.col.f32.f16.f16.f32 "
        "{%0,%1,%2,%3}, {%4,%5,%6,%7}, {%8,%9}, {%0,%1,%2,%3};"
        : "+f"(d[0]), "+f"(d[1]), "+f"(d[2]), "+f"(d[3])
        : "r"(a.x), "r"(a.y), "r"(a.z), "r"(a.w), "r"(b.x), "r"(b.y));
}

// ---------------------------------------------------------------------------
// Prep: encoder weights -> per-chunk fp16 fragment images (single part,
// o padded to 128); compress weights -> [c][m].
// m16n8k16 A frag (row-major): reg = (kk>=8)*2 + (o16>=8),
// lane = (o16&7)*4 + ((kk>>1)&3), half = kk&1.
// ---------------------------------------------------------------------------
__global__ __launch_bounds__(256)
void k_prep(const float* __restrict__ ew, const float* __restrict__ cw) {
    int idx = blockIdx.x * 256 + threadIdx.x;
    if (idx < 128 * KTOT) {
        int o = idx / KTOT, k = idx - o * KTOT;
        float v = (o < 100) ? ew[o * KTOT + k] : 0.f;
        int ch = k / KC, kl = k - ch * KC;
        int ks = kl >> 4, kk = kl & 15;
        int mt = o >> 4, o16 = o & 15;
        int reg = ((kk >> 3) << 1) | (o16 >> 3);
        int lane = (o16 & 7) * 4 + ((kk >> 1) & 3);
        int half = kk & 1;
        int base = (((mt * 3 + ks) * 32 + lane) * 4 + reg) * 2 + half;
        g_afrag[ch * A_CH16 + base] = __half_as_ushort(__float2half_rn(v));
    } else if (idx < 128 * KTOT + CI * MC) {
        int j = idx - 128 * KTOT;
        g_cw2[j] = cw[(j & 63) * CI + (j >> 6)];
    }
}

// ---------------------------------------------------------------------------
// Kernel 1: 1x1 compress conv. block=(h-pair, b), 128 thr (R8 frozen).
// ---------------------------------------------------------------------------
extern __shared__ float sm1[];
__global__ __launch_bounds__(128)
void k_compress(const float* __restrict__ x, const float* __restrict__ cb) {
    float* xs = sm1;
    float* ws = sm1 + CI * 2 * 68;
    const int hb = blockIdx.x, b = blockIdx.y, tid = threadIdx.x;

    const float4* x4 = reinterpret_cast<const float4*>(x) + (size_t)b * (CI * HH * WW / 4);
    for (int idx = tid; idx < CI * 2 * 16; idx += 128) {
        int q = idx & 15, r = (idx >> 4) & 1, c = idx >> 5;
        float4 v = x4[(c * HH + 2 * hb + r) * 16 + q];
        *reinterpret_cast<float4*>(xs + (c * 2 + r) * 68 + q * 4) = v;
    }
    for (int idx = tid; idx < CI * MC / 4; idx += 128)
        reinterpret_cast<float4*>(ws)[idx] = reinterpret_cast<const float4*>(g_cw2)[idx];
    __syncthreads();

    const int mt = tid >> 4, wt = tid & 15;
    const int r = wt >> 3, w0 = (wt & 7) * 8, m0 = mt * 8;

    u64 acc[4][8];
    #pragma unroll
    for (int m = 0; m < 8; m++)
        #pragma unroll
        for (int wp = 0; wp < 4; wp++) acc[wp][m] = 0;

    #pragma unroll 2
    for (int c = 0; c < CI; c++) {
        const float* xr = xs + (c * 2 + r) * 68 + w0;
        u64 X0 = ld2(xr), X1 = ld2(xr + 2), X2 = ld2(xr + 4), X3 = ld2(xr + 6);
        const float* wr = ws + c * 64 + m0;
        #pragma unroll
        for (int m = 0; m < 8; m++) {
            float wv = wr[m];
            u64 W = pk2(wv, wv);
            fma2(acc[0][m], X0, W); fma2(acc[1][m], X1, W);
            fma2(acc[2][m], X2, W); fma2(acc[3][m], X3, W);
        }
    }
    #pragma unroll
    for (int m = 0; m < 8; m++) {
        float bv = cb[m0 + m];
        #pragma unroll
        for (int wp = 0; wp < 4; wp++) {
            float2 v = upk2(acc[wp][m]);
            *reinterpret_cast<float2*>(
                g_m + (((size_t)b * MC + m0 + m) * HH + 2 * hb + r) * WW + w0 + 2 * wp)
                = make_float2(v.x + bv, v.y + bv);
        }
    }
}

// ---------------------------------------------------------------------------
// Kernel 2: encoder conv as fp16 mma.sync GEMM + bias + softmax.
// block=(h2,b) covers an h-pair. D[128o,128n] (n = p*64 + w), K=576 in 12
// chunks of 48 (3 k16-steps). Warps = 4 m-groups x 2 n-groups.
// Single product per step: A(fp16 weights) * B(fp16 m patches).
// ---------------------------------------------------------------------------
__global__ __launch_bounds__(256, 2)
void k_encoder(const float* __restrict__ eb) {
    extern __shared__ __align__(16) uint32_t smE[];
    uint32_t* a_s = smE;             // 3072 u32 (A image)
    uint32_t* b_s = smE + 3072;      // 3072 u32 (B image)
    uint16_t* b_s16 = reinterpret_cast<uint16_t*>(b_s);
    float* kt = reinterpret_cast<float*>(smE);   // alias post-compute: [o][128]
    const int h2 = blockIdx.x, b = blockIdx.y, tid = threadIdx.x;
    const int wid = tid >> 5, lane = tid & 31;
    const int mg = wid >> 1, ngrp = wid & 1;
    const int gg = lane >> 2, tig = lane & 3;

    float acc[2][8][4];
    #pragma unroll
    for (int mt = 0; mt < 2; mt++)
        #pragma unroll
        for (int nt = 0; nt < 8; nt++)
            #pragma unroll
            for (int q = 0; q < 4; q++) acc[mt][nt][q] = 0.f;

    for (int ch = 0; ch < NCH; ch++) {
        __syncthreads();
        // stage A fragment image (12.3 KB)
        {
            const uint4* asrc = reinterpret_cast<const uint4*>(g_afrag + (size_t)ch * A_CH16);
            uint4* adst = reinterpret_cast<uint4*>(a_s);
            for (int idx = tid; idx < A_CH16 / 8; idx += 256) adst[idx] = asrc[idx];
        }
        // build B fragment slots from g_m (fp16)
        for (int idx = tid; idx < KC * 128; idx += 256) {
            int n = idx & 127, kl = idx >> 7;
            int k = ch * KC + kl;
            int c = k / 9, rem = k - c * 9;
            int r = rem / 3, s = rem - r * 3;
            int p = n >> 6, w = n & 63;
            int hh = 2 * h2 + p + r - 1, col = w + s - 1;
            float v = 0.f;
            if ((unsigned)hh < HH && (unsigned)col < WW)
                v = g_m[(((size_t)b * MC + c) * HH + hh) * WW + col];
            int ks = kl >> 4, kk = kl & 15;
            int ntg = n >> 3, n8 = n & 7;
            int reg = kk >> 3;
            int lne = n8 * 4 + ((kk >> 1) & 3);
            b_s16[(((ks * 16 + ntg) * 32 + lne) * 2 + reg) * 2 + (kk & 1)] =
                __half_as_ushort(__float2half_rn(v));
        }
        __syncthreads();

        #pragma unroll
        for (int ks = 0; ks < 3; ks++) {
            uint4 A1[2];
            #pragma unroll
            for (int mt = 0; mt < 2; mt++) {
                int mtg = mg * 2 + mt;
                A1[mt] = *reinterpret_cast<const uint4*>(a_s + ((mtg * 3 + ks) * 32 + lane) * 4);
            }
            #pragma unroll
            for (int nt = 0; nt < 8; nt++) {
                int ntg = ngrp * 8 + nt;
                uint2 Bv = *reinterpret_cast<const uint2*>(b_s + ((ks * 16 + ntg) * 32 + lane) * 2);
                #pragma unroll
                for (int mt = 0; mt < 2; mt++)
                    mma16(acc[mt][nt], A1[mt], Bv);
            }
        }
    }
    __syncthreads();

    // writeout D -> kt[o][n] (+bias), per fragment mapping
    #pragma unroll
    for (int mt = 0; mt < 2; mt++) {
        #pragma unroll
        for (int nt = 0; nt < 8; nt++) {
            int o0 = (mg * 2 + mt) * 16 + gg;
            int n0 = (ngrp * 8 + nt) * 8 + 2 * tig;
            const float* c = acc[mt][nt];
            if (o0 < 100) {
                float bv = __ldg(eb + o0);
                kt[o0 * 128 + n0] = c[0] + bv;
                kt[o0 * 128 + n0 + 1] = c[1] + bv;
            }
            int o1 = o0 + 8;
            if (o1 < 100) {
                float bv = __ldg(eb + o1);
                kt[o1 * 128 + n0] = c[2] + bv;
                kt[o1 * 128 + n0 + 1] = c[3] + bv;
            }
        }
    }
    __syncthreads();

    // softmax over 25 taps: 512 tasks = p(2) x sub(4) x w(64)
    for (int task = tid; task < 512; task += 256) {
        int w2 = task & 63, sub = (task >> 6) & 3, p = task >> 8;
        int colk = p * 64 + w2;
        int sh = sub >> 1, sw = sub & 1;
        float v[25]; float mx = -1e30f;
        #pragma unroll
        for (int t = 0; t < 25; t++) {
            v[t] = kt[(t * 4 + sub) * 128 + colk];
            mx = fmaxf(mx, v[t]);
        }
        float ssum = 0.f;
        #pragma unroll
        for (int t = 0; t < 25; t++) { v[t] = __expf(v[t] - mx); ssum += v[t]; }
        float inv = 1.f / ssum;
        int oh = 4 * h2 + 2 * p + sh, ow = 2 * w2 + sw;
        #pragma unroll
        for (int t = 0; t < 25; t++)
            g_ker[(((size_t)b * 25 + t) * NH + oh) * NW + ow] = v[t] * inv;
    }
}

// ---------------------------------------------------------------------------
// Kernel 3: content-aware reassembly (R8 frozen). block=(h, cg, b): 16 ch,
// 256 thr, ~48 KB smem -> 4 blocks/SM.
// ---------------------------------------------------------------------------
extern __shared__ float sm3[];
__global__ __launch_bounds__(256, 4)
void k_carafe(const float* __restrict__ x, float* __restrict__ out) {
    float* ker_s = sm3;           // 50*128
    float* x_s   = sm3 + 6400;    // 80*72
    const int h = blockIdx.x, cg = blockIdx.y, b = blockIdx.z, tid = threadIdx.x;
    const int cbase = cg * 16;

    for (int idx = tid; idx < 50 * 32; idx += 256) {
        int q = idx & 31, tp = idx >> 5;
        *reinterpret_cast<float4*>(ker_s + tp * 128 + q * 4) =
            *reinterpret_cast<const float4*>(
                g_ker + (((size_t)b * 25 + (tp >> 1)) * NH + 2 * h + (tp & 1)) * NW + q * 4);
    }
    for (int idx = tid; idx < 16 * 5 * 16; idx += 256) {
        int q = idx & 15, row = idx >> 4;
        int c = row / 5, i = row - c * 5;
        int hh = h + i - 2;
        float4 v = make_float4(0.f, 0.f, 0.f, 0.f);
        if ((unsigned)hh < HH)
            v = *reinterpret_cast<const float4*>(
                x + (((size_t)b * CI + cbase + c) * HH + hh) * WW + q * 4);
        *reinterpret_cast<float4*>(x_s + row * 72 + 4 + q * 4) = v;
    }
    for (int idx = tid; idx < 160; idx += 256) {
        int row = idx >> 1, e = idx & 1;
        *reinterpret_cast<float4*>(x_s + row * 72 + (e ? 68 : 0)) =
            make_float4(0.f, 0.f, 0.f, 0.f);
    }
    __syncthreads();

    const int w = tid & 63, co = tid >> 6;
    const float* kb = ker_s + 2 * w;
    const float* xb = x_s + (size_t)(co * 4) * 360 + w + 2;

    u64 acc[2][4];
    #pragma unroll
    for (int p = 0; p < 2; p++)
        #pragma unroll
        for (int cc = 0; cc < 4; cc++) acc[p][cc] = 0;

    #pragma unroll
    for (int i = 0; i < 5; i++) {
        #pragma unroll
        for (int j = 0; j < 5; j++) {
            const int t = i * 5 + j;
            u64 K0 = ld2(kb + (2 * t) * 128);
            u64 K1 = ld2(kb + (2 * t + 1) * 128);
            #pragma unroll
            for (int cc = 0; cc < 4; cc++) {
                float xv = xb[cc * 360 + i * 72 + j];
                u64 X = pk2(xv, xv);
                fma2(acc[0][cc], X, K0);
                fma2(acc[1][cc], X, K1);
            }
        }
    }
    #pragma unroll
    for (int p = 0; p < 2; p++)
        #pragma unroll
        for (int cc = 0; cc < 4; cc++) {
            float2 v = upk2(acc[p][cc]);
            int ch = cbase + co * 4 + cc;
            *reinterpret_cast<float2*>(
                out + (((size_t)b * CI + ch) * NH + 2 * h + p) * NW + 2 * w) = v;
        }
}

// ---------------------------------------------------------------------------
extern "C" void kernel_launch(void* const* d_in, const int* in_sizes, int n_in,
                              void* d_out, int out_size) {
    const float* x  = (const float*)d_in[0];
    const float* cw = (const float*)d_in[1];
    const float* cb = (const float*)d_in[2];
    const float* ew = (const float*)d_in[3];
    const float* eb = (const float*)d_in[4];
    float* out = (float*)d_out;

    const int smem1 = (CI * 2 * 68 + CI * MC) * 4;     // 102400
    const int smem3 = (6400 + 80 * 72) * 4;            // 48640
    cudaFuncSetAttribute(k_compress, cudaFuncAttributeMaxDynamicSharedMemorySize, smem1);
    cudaFuncSetAttribute(k_encoder,  cudaFuncAttributeMaxDynamicSharedMemorySize, SMEM_ENC);
    cudaFuncSetAttribute(k_carafe,   cudaFuncAttributeMaxDynamicSharedMemorySize, smem3);

    k_prep<<<(128 * KTOT + CI * MC + 255) / 256, 256>>>(ew, cw);
    k_compress<<<dim3(HH / 2, BB), 128, smem1>>>(x, cb);
    k_encoder<<<dim3(HH / 2, BB), 256, SMEM_ENC>>>(eb);
    k_carafe<<<dim3(HH, 8, BB), 256, smem3>>>(x, out);
}